// round 2
// baseline (speedup 1.0000x reference)
#include <cuda_runtime.h>
#include <math.h>

#define BATCH 16
#define CHAN 512
#define HW 1024
#define O3 1536
#define HEADS 4
#define DHEAD 128
#define SEQ 1024
#define SCALE 0.08838834764831845f   // 128^-0.5

// Scratch: Q (scale folded in), K (pos-emb folded in), V. [b, head, seq, d]
__device__ float g_Q[BATCH * HEADS * SEQ * DHEAD];
__device__ float g_K[BATCH * HEADS * SEQ * DHEAD];
__device__ float g_V[BATCH * HEADS * SEQ * DHEAD];

// ---------------------------------------------------------------------------
// Kernel 1: qkv[b,o,p] = sum_c w[o,c] * fmap[b,c,p]; scatter into g_Q/g_K/g_V
// with scale folded into Q and emb folded into K.
// Block: 64(o) x 64(p) tile, 256 threads, 4x4 per thread, K-chunks of 16.
// ---------------------------------------------------------------------------
__global__ __launch_bounds__(256) void qkv_kernel(
    const float* __restrict__ fmap, const float* __restrict__ w,
    const float* __restrict__ height, const float* __restrict__ width)
{
    __shared__ float Ws[16][65];   // [kc][o_local], padded vs STS conflicts
    __shared__ float Fs[16][64];   // [kc][p_local]
    __shared__ float Ts[64][65];   // transpose buffer [p_local][o_local]

    const int b  = blockIdx.z;
    const int o0 = blockIdx.y * 64;
    const int p0 = blockIdx.x * 64;
    const int tid = threadIdx.x;
    const int tx = tid & 15, ty = tid >> 4;

    float acc[4][4];
#pragma unroll
    for (int r = 0; r < 4; r++)
#pragma unroll
        for (int c = 0; c < 4; c++) acc[r][c] = 0.0f;

    const float* Fb = fmap + (size_t)b * CHAN * HW;
    const int cl = tid & 15, ol = tid >> 4;   // W tile loader coords
    const int pl = tid & 63, kl = tid >> 6;   // F tile loader coords

    for (int k0 = 0; k0 < CHAN; k0 += 16) {
#pragma unroll
        for (int pass = 0; pass < 4; pass++)
            Ws[cl][ol + pass * 16] = w[(size_t)(o0 + ol + pass * 16) * CHAN + k0 + cl];
#pragma unroll
        for (int pass = 0; pass < 4; pass++)
            Fs[kl + pass * 4][pl] = Fb[(size_t)(k0 + kl + pass * 4) * HW + p0 + pl];
        __syncthreads();

#pragma unroll
        for (int kc = 0; kc < 16; kc++) {
            const float a0 = Ws[kc][ty * 4 + 0];
            const float a1 = Ws[kc][ty * 4 + 1];
            const float a2 = Ws[kc][ty * 4 + 2];
            const float a3 = Ws[kc][ty * 4 + 3];
            const float4 b4 = *(const float4*)&Fs[kc][tx * 4];
            acc[0][0] += a0 * b4.x; acc[0][1] += a0 * b4.y; acc[0][2] += a0 * b4.z; acc[0][3] += a0 * b4.w;
            acc[1][0] += a1 * b4.x; acc[1][1] += a1 * b4.y; acc[1][2] += a1 * b4.z; acc[1][3] += a1 * b4.w;
            acc[2][0] += a2 * b4.x; acc[2][1] += a2 * b4.y; acc[2][2] += a2 * b4.z; acc[2][3] += a2 * b4.w;
            acc[3][0] += a3 * b4.x; acc[3][1] += a3 * b4.y; acc[3][2] += a3 * b4.z; acc[3][3] += a3 * b4.w;
        }
        __syncthreads();
    }

    // Transpose tile in smem so the scatter write has d contiguous per p.
#pragma unroll
    for (int r = 0; r < 4; r++)
#pragma unroll
        for (int c = 0; c < 4; c++)
            Ts[tx * 4 + c][ty * 4 + r] = acc[r][c];
    __syncthreads();

    const int prow  = tid >> 2;           // 0..63
    const int ocol0 = (tid & 3) * 16;     // 0,16,32,48
    const int p  = p0 + prow;
    const int xh = p >> 5, yw = p & 31;
#pragma unroll
    for (int u = 0; u < 16; u++) {
        const int o = o0 + ocol0 + u;
        const float v = Ts[prow][ocol0 + u];
        const int part = o >> 9;          // 0=q 1=k 2=v
        const int head = (o >> 7) & 3;
        const int d    = o & 127;
        const size_t idx = ((size_t)(b * HEADS + head) * SEQ + p) * DHEAD + d;
        if (part == 0)       g_Q[idx] = v * SCALE;
        else if (part == 1)  g_K[idx] = v + height[xh * DHEAD + d] + width[yw * DHEAD + d];
        else                 g_V[idx] = v;
    }
}

// ---------------------------------------------------------------------------
// Kernel 2: flash attention, fp32. Br=Bc=64, d=128.
// Block 256 threads: (ty,tx) in 16x16; S tile 4x4/thread, O tile 4x8/thread.
// ---------------------------------------------------------------------------
#define QP 132   // 128 + 4 pad (keeps float4 alignment)
#define PP 68    // 64 + 4 pad

#define SMEM2 ((3 * 64 * QP + 64 * PP) * 4)

__global__ __launch_bounds__(256) void attn_kernel(float* __restrict__ out)
{
    extern __shared__ float sm[];
    float* Qs = sm;                  // 64 x QP
    float* Ks = sm + 64 * QP;        // 64 x QP
    float* Vs = sm + 2 * 64 * QP;    // 64 x QP
    float* Ps = sm + 3 * 64 * QP;    // 64 x PP

    const int bh  = blockIdx.y;               // b*4 + head
    const int i0  = blockIdx.x * 64;
    const int tid = threadIdx.x;
    const int tx = tid & 15, ty = tid >> 4;

    const size_t base = (size_t)bh * SEQ * DHEAD;

    {   // load Q tile (64 x 128 -> padded rows)
        const float* Qg = g_Q + base + (size_t)i0 * DHEAD;
#pragma unroll
        for (int pass = 0; pass < 8; pass++) {
            const int vi = tid + pass * 256;       // 0..2047 float4 slots
            const int row = vi >> 5, col = (vi & 31) << 2;
            *(float4*)&Qs[row * QP + col] = *(const float4*)&Qg[row * DHEAD + col];
        }
    }

    float m[4], l[4], o[4][8];
#pragma unroll
    for (int r = 0; r < 4; r++) {
        m[r] = -1e30f; l[r] = 0.0f;
#pragma unroll
        for (int c = 0; c < 8; c++) o[r][c] = 0.0f;
    }

    for (int jt = 0; jt < SEQ; jt += 64) {
        __syncthreads();   // previous P@V done before reloading K/V
        const float* Kg = g_K + base + (size_t)jt * DHEAD;
        const float* Vg = g_V + base + (size_t)jt * DHEAD;
#pragma unroll
        for (int pass = 0; pass < 8; pass++) {
            const int vi = tid + pass * 256;
            const int row = vi >> 5, col = (vi & 31) << 2;
            *(float4*)&Ks[row * QP + col] = *(const float4*)&Kg[row * DHEAD + col];
            *(float4*)&Vs[row * QP + col] = *(const float4*)&Vg[row * DHEAD + col];
        }
        __syncthreads();

        // S = Qs @ Ks^T  (4x4 per thread)
        float s[4][4];
#pragma unroll
        for (int r = 0; r < 4; r++)
#pragma unroll
            for (int c = 0; c < 4; c++) s[r][c] = 0.0f;

        for (int d = 0; d < DHEAD; d += 4) {
            float4 q0 = *(const float4*)&Qs[(ty * 4 + 0) * QP + d];
            float4 q1 = *(const float4*)&Qs[(ty * 4 + 1) * QP + d];
            float4 q2 = *(const float4*)&Qs[(ty * 4 + 2) * QP + d];
            float4 q3 = *(const float4*)&Qs[(ty * 4 + 3) * QP + d];
            float4 k0 = *(const float4*)&Ks[(tx * 4 + 0) * QP + d];
            float4 k1 = *(const float4*)&Ks[(tx * 4 + 1) * QP + d];
            float4 k2 = *(const float4*)&Ks[(tx * 4 + 2) * QP + d];
            float4 k3 = *(const float4*)&Ks[(tx * 4 + 3) * QP + d];
#define DOT4(S, Q, K) S += Q.x*K.x + Q.y*K.y + Q.z*K.z + Q.w*K.w
            DOT4(s[0][0], q0, k0); DOT4(s[0][1], q0, k1); DOT4(s[0][2], q0, k2); DOT4(s[0][3], q0, k3);
            DOT4(s[1][0], q1, k0); DOT4(s[1][1], q1, k1); DOT4(s[1][2], q1, k2); DOT4(s[1][3], q1, k3);
            DOT4(s[2][0], q2, k0); DOT4(s[2][1], q2, k1); DOT4(s[2][2], q2, k2); DOT4(s[2][3], q2, k3);
            DOT4(s[3][0], q3, k0); DOT4(s[3][1], q3, k1); DOT4(s[3][2], q3, k2); DOT4(s[3][3], q3, k3);
#undef DOT4
        }

        // online softmax (row stats via 16-lane xor shuffles)
#pragma unroll
        for (int r = 0; r < 4; r++) {
            float mx = fmaxf(fmaxf(s[r][0], s[r][1]), fmaxf(s[r][2], s[r][3]));
#pragma unroll
            for (int off = 8; off >= 1; off >>= 1)
                mx = fmaxf(mx, __shfl_xor_sync(0xffffffffu, mx, off));
            const float mnew = fmaxf(m[r], mx);
            const float p0 = __expf(s[r][0] - mnew);
            const float p1 = __expf(s[r][1] - mnew);
            const float p2 = __expf(s[r][2] - mnew);
            const float p3 = __expf(s[r][3] - mnew);
            float rs = p0 + p1 + p2 + p3;
#pragma unroll
            for (int off = 8; off >= 1; off >>= 1)
                rs += __shfl_xor_sync(0xffffffffu, rs, off);
            const float alpha = __expf(m[r] - mnew);
            l[r] = l[r] * alpha + rs;
            m[r] = mnew;
#pragma unroll
            for (int c = 0; c < 8; c++) o[r][c] *= alpha;
            float* prow = &Ps[(ty * 4 + r) * PP + tx * 4];
            prow[0] = p0; prow[1] = p1; prow[2] = p2; prow[3] = p3;
        }
        __syncthreads();

        // O += P @ V  (rows ty*4.., cols tx*8..)
#pragma unroll 4
        for (int j = 0; j < 64; j++) {
            const float4 va = *(const float4*)&Vs[j * QP + tx * 8];
            const float4 vb = *(const float4*)&Vs[j * QP + tx * 8 + 4];
#pragma unroll
            for (int r = 0; r < 4; r++) {
                const float pr = Ps[(ty * 4 + r) * PP + j];
                o[r][0] += pr * va.x; o[r][1] += pr * va.y;
                o[r][2] += pr * va.z; o[r][3] += pr * va.w;
                o[r][4] += pr * vb.x; o[r][5] += pr * vb.y;
                o[r][6] += pr * vb.z; o[r][7] += pr * vb.w;
            }
        }
    }

    // epilogue: normalize, transpose via smem (reuse Qs/Ks region), write
    __syncthreads();
    float* OsT = sm;   // 128 x 65
#pragma unroll
    for (int r = 0; r < 4; r++) {
        const float inv = 1.0f / l[r];
#pragma unroll
        for (int c = 0; c < 8; c++)
            OsT[(tx * 8 + c) * 65 + ty * 4 + r] = o[r][c] * inv;
    }
    __syncthreads();

    const int b = bh >> 2, head = bh & 3;
    const int drow  = tid >> 1;            // 0..127
    const int icol0 = (tid & 1) * 32;
    float* og = out + ((size_t)b * (HEADS * DHEAD) + head * DHEAD + drow) * HW + i0 + icol0;
    const float* src = &OsT[drow * 65 + icol0];
#pragma unroll
    for (int u = 0; u < 32; u++) og[u] = src[u];
}

// ---------------------------------------------------------------------------
extern "C" void kernel_launch(void* const* d_in, const int* in_sizes, int n_in,
                              void* d_out, int out_size)
{
    const float* fmap   = (const float*)d_in[0];
    const float* w_qkv  = (const float*)d_in[1];
    const float* height = (const float*)d_in[2];
    const float* width  = (const float*)d_in[3];
    float* out = (float*)d_out;

    cudaFuncSetAttribute(attn_kernel, cudaFuncAttributeMaxDynamicSharedMemorySize, SMEM2);

    qkv_kernel<<<dim3(HW / 64, O3 / 64, BATCH), 256>>>(fmap, w_qkv, height, width);
    attn_kernel<<<dim3(SEQ / 64, BATCH * HEADS), 256, SMEM2>>>(out);
}